// round 10
// baseline (speedup 1.0000x reference)
#include <cuda_runtime.h>
#include <cstdint>

#define N_NODES 50000
#define N_EDGES 800000
#define FDIM    64
#define NRELS   8
#define NB      (NRELS * N_NODES)   // 400000 buckets, key = r*N + dst

// ---- scratch (allocation-free rule: __device__ globals) ----
__device__ int g_cnt[NB];        // bucket histogram
__device__ int g_off[NB + 1];    // exclusive prefix (bucket offsets)
__device__ int g_cur[NB];        // reorder cursors
__device__ int g_bsum[512];      // scan block sums
__device__ int g_ssrc[N_EDGES];  // src indices sorted by bucket
__device__ int g_deg[N_NODES];   // in-degree per dst

// ---------------------------------------------------------------------------
// P0: zero histogram + degree.
// ---------------------------------------------------------------------------
__global__ void k_zero_cnt() {
    int i = blockIdx.x * blockDim.x + threadIdx.x;
    if (i < NB) g_cnt[i] = 0;
    if (i < N_NODES) g_deg[i] = 0;
}

// ---------------------------------------------------------------------------
// P1: bucket histogram + degree histogram.
// ---------------------------------------------------------------------------
__global__ void k_hist(const int* __restrict__ dst, const int* __restrict__ et) {
    int e = blockIdx.x * blockDim.x + threadIdx.x;
    if (e >= N_EDGES) return;
    int d = dst[e];
    atomicAdd(&g_cnt[et[e] * N_NODES + d], 1);
    atomicAdd(&g_deg[d], 1);
}

// ---------------------------------------------------------------------------
// P2..P4: exclusive prefix sum of g_cnt -> g_off (two-level Hillis-Steele).
// ---------------------------------------------------------------------------
#define SCAN_BLK 1024
#define SCAN_NBLK ((NB + SCAN_BLK - 1) / SCAN_BLK)   // 391

__global__ __launch_bounds__(SCAN_BLK) void k_scan1() {
    __shared__ int sm[SCAN_BLK];
    int i = blockIdx.x * SCAN_BLK + threadIdx.x;
    int v = (i < NB) ? g_cnt[i] : 0;
    sm[threadIdx.x] = v;
    __syncthreads();
    #pragma unroll
    for (int d = 1; d < SCAN_BLK; d <<= 1) {
        int t = (threadIdx.x >= d) ? sm[threadIdx.x - d] : 0;
        __syncthreads();
        sm[threadIdx.x] += t;
        __syncthreads();
    }
    int incl = sm[threadIdx.x];
    if (i < NB) g_off[i] = incl - v;                       // exclusive
    if (threadIdx.x == SCAN_BLK - 1) g_bsum[blockIdx.x] = incl;
}

__global__ __launch_bounds__(512) void k_scan2() {
    __shared__ int sm[512];
    int v = (threadIdx.x < SCAN_NBLK) ? g_bsum[threadIdx.x] : 0;
    sm[threadIdx.x] = v;
    __syncthreads();
    #pragma unroll
    for (int d = 1; d < 512; d <<= 1) {
        int t = (threadIdx.x >= d) ? sm[threadIdx.x - d] : 0;
        __syncthreads();
        sm[threadIdx.x] += t;
        __syncthreads();
    }
    if (threadIdx.x < SCAN_NBLK) g_bsum[threadIdx.x] = sm[threadIdx.x] - v;
}

__global__ void k_scan3() {
    int i = blockIdx.x * blockDim.x + threadIdx.x;
    if (i < NB) {
        int o = g_off[i] + g_bsum[i >> 10];
        g_off[i] = o;
        g_cur[i] = o;
    }
    if (i == 0) g_off[NB] = N_EDGES;
}

// ---------------------------------------------------------------------------
// P5: reorder src by bucket (counting-sort placement).
// ---------------------------------------------------------------------------
__global__ void k_reorder(const int* __restrict__ src, const int* __restrict__ dst,
                          const int* __restrict__ et) {
    int e = blockIdx.x * blockDim.x + threadIdx.x;
    if (e >= N_EDGES) return;
    int pos = atomicAdd(&g_cur[et[e] * N_NODES + dst[e]], 1);
    g_ssrc[pos] = src[e];
}

// ---------------------------------------------------------------------------
// MAIN: fused gather + tf32 GEMM + epilogue. Block = 128 nodes x 64 cols,
// 256 threads (8 warps, one m16 row-tile each).
// Per relation slice rs:
//   - stage W_rs in smem (stride 72, conflict-free B-frag LDS, pre-tf32)
//   - 16 thread-groups of 16 lanes gather-sum feat[src] over bucket
//     (rs, node) into smem A-tile (stride 68, conflict-free A-frag LDS)
//   - mma.m16n8k8 slice, accumulate in registers
// Epilogue: out = deg>0 ? relu(0.2*feat + (0.8/deg)*M) : feat
// ---------------------------------------------------------------------------
#define GT 256
#define A_STRIDE 68
#define W_STRIDE 72
#define FUSED_SMEM ((128 * A_STRIDE + FDIM * W_STRIDE) * 4)  // 34816+18432=53248

__device__ __forceinline__ uint32_t f2tf32(float x) {
    uint32_t u;
    asm("cvt.rna.tf32.f32 %0, %1;" : "=r"(u) : "f"(x));
    return u;
}

__global__ __launch_bounds__(GT)
void k_fused(const float* __restrict__ feat, const float* __restrict__ W,
             float* __restrict__ out) {
    extern __shared__ float smraw[];
    float (*As)[A_STRIDE] = (float (*)[A_STRIDE])smraw;          // [128][68]
    uint32_t* Ws = (uint32_t*)(smraw + 128 * A_STRIDE);          // [64][72]

    const float4* feat4 = (const float4*)feat;
    const int row0 = blockIdx.x * 128;
    const int tid  = threadIdx.x;
    const int warp = tid >> 5;
    const int lane = tid & 31;
    const int gid  = lane >> 2;   // 0..7
    const int kc   = lane & 3;    // 0..3
    const int grp  = tid >> 4;    // 0..15 (gather group)
    const int gl   = tid & 15;    // lane in group -> one float4 column

    float c[8][4];
    #pragma unroll
    for (int nt = 0; nt < 8; nt++)
        #pragma unroll
        for (int i = 0; i < 4; i++) c[nt][i] = 0.f;

    for (int rs = 0; rs < NRELS; rs++) {
        __syncthreads();   // protect As/Ws from previous slice's readers

        // stage W_rs (pre-rounded to tf32)
        const float* Wg = W + (size_t)rs * FDIM * FDIM;
        #pragma unroll
        for (int i = tid; i < FDIM * FDIM; i += GT)
            Ws[(i >> 6) * W_STRIDE + (i & 63)] = f2tf32(Wg[i]);

        // prefetch bucket bounds for this group's 8 nodes (MLP)
        int s0[8], s1[8];
        #pragma unroll
        for (int it = 0; it < 8; it++) {
            int d = row0 + it * 16 + grp;
            if (d < N_NODES) {
                int b = rs * N_NODES + d;
                s0[it] = __ldg(&g_off[b]);
                s1[it] = __ldg(&g_off[b + 1]);
            } else {
                s0[it] = 0; s1[it] = 0;
            }
        }

        // gather-sum feat rows into A-tile
        #pragma unroll
        for (int it = 0; it < 8; it++) {
            float4 acc = make_float4(0.f, 0.f, 0.f, 0.f);
            int p = s0[it], pe = s1[it];
            for (; p + 1 < pe; p += 2) {   // unroll x2 for load overlap
                int sa = __ldg(&g_ssrc[p]);
                int sb = __ldg(&g_ssrc[p + 1]);
                float4 va = __ldg(&feat4[(size_t)sa * 16 + gl]);
                float4 vb = __ldg(&feat4[(size_t)sb * 16 + gl]);
                acc.x += va.x + vb.x; acc.y += va.y + vb.y;
                acc.z += va.z + vb.z; acc.w += va.w + vb.w;
            }
            if (p < pe) {
                int sa = __ldg(&g_ssrc[p]);
                float4 va = __ldg(&feat4[(size_t)sa * 16 + gl]);
                acc.x += va.x; acc.y += va.y; acc.z += va.z; acc.w += va.w;
            }
            *(float4*)&As[it * 16 + grp][gl * 4] = acc;   // 272B stride: 16B aligned
        }
        __syncthreads();

        // tf32 mma over the 64-wide K slice
        const int wr = warp * 16;
        #pragma unroll
        for (int ks = 0; ks < 8; ks++) {
            const int k0 = ks * 8;
            uint32_t a0 = f2tf32(As[wr + gid][k0 + kc]);
            uint32_t a1 = f2tf32(As[wr + gid + 8][k0 + kc]);
            uint32_t a2 = f2tf32(As[wr + gid][k0 + kc + 4]);
            uint32_t a3 = f2tf32(As[wr + gid + 8][k0 + kc + 4]);
            #pragma unroll
            for (int nt = 0; nt < 8; nt++) {
                uint32_t b0 = Ws[(k0 + kc) * W_STRIDE + nt * 8 + gid];
                uint32_t b1 = Ws[(k0 + kc + 4) * W_STRIDE + nt * 8 + gid];
                asm volatile(
                    "mma.sync.aligned.m16n8k8.row.col.f32.tf32.tf32.f32 "
                    "{%0,%1,%2,%3}, {%4,%5,%6,%7}, {%8,%9}, {%0,%1,%2,%3};"
                    : "+f"(c[nt][0]), "+f"(c[nt][1]), "+f"(c[nt][2]), "+f"(c[nt][3])
                    : "r"(a0), "r"(a1), "r"(a2), "r"(a3), "r"(b0), "r"(b1));
            }
        }
    }

    // fused epilogue
    {
        int r0 = row0 + warp * 16 + gid;
        int r1 = r0 + 8;
        bool v0 = r0 < N_NODES, v1 = r1 < N_NODES;
        int dg0 = v0 ? g_deg[r0] : 0;
        int dg1 = v1 ? g_deg[r1] : 0;
        float inv0 = dg0 > 0 ? 0.8f / (float)dg0 : 0.f;
        float inv1 = dg1 > 0 ? 0.8f / (float)dg1 : 0.f;
        #pragma unroll
        for (int nt = 0; nt < 8; nt++) {
            int col = nt * 8 + 2 * kc;
            if (v0) {
                float2 f = *(const float2*)&feat[(size_t)r0 * FDIM + col];
                float2 o;
                if (dg0 > 0) {
                    o.x = fmaxf(fmaf(c[nt][0], inv0, 0.2f * f.x), 0.f);
                    o.y = fmaxf(fmaf(c[nt][1], inv0, 0.2f * f.y), 0.f);
                } else o = f;
                *(float2*)&out[(size_t)r0 * FDIM + col] = o;
            }
            if (v1) {
                float2 f = *(const float2*)&feat[(size_t)r1 * FDIM + col];
                float2 o;
                if (dg1 > 0) {
                    o.x = fmaxf(fmaf(c[nt][2], inv1, 0.2f * f.x), 0.f);
                    o.y = fmaxf(fmaf(c[nt][3], inv1, 0.2f * f.y), 0.f);
                } else o = f;
                *(float2*)&out[(size_t)r1 * FDIM + col] = o;
            }
        }
    }
}

// ---------------------------------------------------------------------------
extern "C" void kernel_launch(void* const* d_in, const int* in_sizes, int n_in,
                              void* d_out, int out_size) {
    const float* feat = (const float*)d_in[0];   // [50000, 64] f32
    const float* W    = (const float*)d_in[1];   // [8, 64, 64] f32
    const int*   src  = (const int*)d_in[2];     // [800000] i32
    const int*   dst  = (const int*)d_in[3];     // [800000] i32
    const int*   et   = (const int*)d_in[4];     // [800000] i32
    float* out = (float*)d_out;                  // [50000, 64] f32

    static bool attr_set = false;
    if (!attr_set) {
        cudaFuncSetAttribute(k_fused, cudaFuncAttributeMaxDynamicSharedMemorySize,
                             FUSED_SMEM);
        attr_set = true;
    }

    k_zero_cnt<<<(NB + 255) / 256, 256>>>();
    k_hist<<<(N_EDGES + 255) / 256, 256>>>(dst, et);
    k_scan1<<<SCAN_NBLK, SCAN_BLK>>>();
    k_scan2<<<1, 512>>>();
    k_scan3<<<(NB + 255) / 256, 256>>>();
    k_reorder<<<(N_EDGES + 255) / 256, 256>>>(src, dst, et);
    k_fused<<<(N_NODES + 127) / 128, GT, FUSED_SMEM>>>(feat, W, out);
}

// round 11
// speedup vs baseline: 1.1240x; 1.1240x over previous
#include <cuda_runtime.h>
#include <cstdint>

#define N_NODES 50000
#define N_EDGES 800000
#define FDIM    64
#define NRELS   8
#define KDIM    (NRELS * FDIM)   // 512

// ---- scratch (allocation-free rule: __device__ globals) ----
// S[n, r, d] node-major accumulator = [50000, 512] fp32 (102.4 MB).
__device__ __align__(16) float g_S[(size_t)N_NODES * KDIM];
__device__ __align__(16) int2  g_epack[N_EDGES];   // {src, dst*8+etype}
__device__ int g_deg[N_NODES];

// ---------------------------------------------------------------------------
// K0: zero the scatter accumulator S and the degree array.
// ---------------------------------------------------------------------------
__global__ void k_zero() {
    size_t i = (size_t)blockIdx.x * blockDim.x + threadIdx.x;
    if (i < (size_t)N_NODES * (KDIM / 4))
        ((float4*)g_S)[i] = make_float4(0.f, 0.f, 0.f, 0.f);
    if (i < N_NODES) g_deg[i] = 0;
}

// ---------------------------------------------------------------------------
// K1: fused degree histogram + edge-index packing.
// g_epack[e] = { src (feat row), dst*8+etype (S row) }.
// ---------------------------------------------------------------------------
__global__ void k_pack_deg(const int* __restrict__ src, const int* __restrict__ dst,
                           const int* __restrict__ et) {
    int e = blockIdx.x * blockDim.x + threadIdx.x;
    if (e >= N_EDGES) return;
    int d = dst[e];
    g_epack[e] = make_int2(src[e], d * NRELS + et[e]);
    atomicAdd(&g_deg[d], 1);
}

// ---------------------------------------------------------------------------
// K2: edge scatter of RAW features. 16 lanes per edge, one float4 each.
// Gather source = feat (12.8 MB, L2-resident). RED target = g_S (dirty-L2).
// ---------------------------------------------------------------------------
__global__ void k_scatter(const float4* __restrict__ feat4) {
    int t = blockIdx.x * blockDim.x + threadIdx.x;
    int e = t >> 4;
    int l = t & 15;
    if (e >= N_EDGES) return;
    int2 idx = __ldg(&g_epack[e]);
    float4 v = __ldg(&feat4[(size_t)idx.x * (FDIM / 4) + l]);
    float* o = g_S + (size_t)idx.y * FDIM + l * 4;
    asm volatile("red.global.add.v4.f32 [%0], {%1,%2,%3,%4};"
                 :: "l"(o), "f"(v.x), "f"(v.y), "f"(v.z), "f"(v.w) : "memory");
}

// ---------------------------------------------------------------------------
// K3: fused GEMM + epilogue, SMEM-STAGED A.
//   M = S[50000, 512] @ Wcat[512, 64]; out = deg>0 ? relu(0.2f + 0.8/deg*M) : f
// Block = 128 rows x 64 cols, 256 threads (8 warps, one m16 tile each).
// Per relation slice: stage W (stride 72, pre-tf32) + stage the 128x64 S
// slice via 2048 coalesced float4 LDGs into As (stride 68 floats = 272B,
// 16B-aligned rows, conflict-free A-frag LDS). tf32 cvt at the smem read.
// ---------------------------------------------------------------------------
#define GT 256
#define A_STRIDE 68
#define W_STRIDE 72
#define GEMM_SMEM ((128 * A_STRIDE + FDIM * W_STRIDE) * 4)  // 34816+18432=53248

__device__ __forceinline__ uint32_t f2tf32(float x) {
    uint32_t u;
    asm("cvt.rna.tf32.f32 %0, %1;" : "=r"(u) : "f"(x));
    return u;
}

__global__ __launch_bounds__(GT)
void k_gemm_final(const float* __restrict__ feat, const float* __restrict__ W,
                  float* __restrict__ out) {
    extern __shared__ float smraw[];
    float (*As)[A_STRIDE] = (float (*)[A_STRIDE])smraw;      // [128][68]
    uint32_t* Ws = (uint32_t*)(smraw + 128 * A_STRIDE);      // [64][72]

    const float4* S4 = (const float4*)g_S;                   // row = 128 float4
    const int row0 = blockIdx.x * 128;
    const int tid  = threadIdx.x;
    const int warp = tid >> 5;     // 0..7
    const int lane = tid & 31;
    const int gid  = lane >> 2;    // 0..7
    const int kc   = lane & 3;     // 0..3
    const int wr   = warp * 16;

    float c[8][4];
    #pragma unroll
    for (int nt = 0; nt < 8; nt++)
        #pragma unroll
        for (int i = 0; i < 4; i++) c[nt][i] = 0.f;

    for (int rs = 0; rs < NRELS; rs++) {
        __syncthreads();   // protect As/Ws from previous slice's readers

        // stage W_rs pre-rounded to tf32 (16 elems/thread)
        const float* Wg = W + (size_t)rs * FDIM * FDIM;
        #pragma unroll
        for (int i = tid; i < FDIM * FDIM; i += GT)
            Ws[(i >> 6) * W_STRIDE + (i & 63)] = f2tf32(Wg[i]);

        // stage the 128x64 S slice: 2048 float4, 8 per thread, coalesced.
        // Rows past N clamped (loads in-bounds; epilogue stores predicated).
        #pragma unroll
        for (int i = tid; i < 128 * 16; i += GT) {
            int rr = i >> 4, cc = i & 15;
            int n = row0 + rr;
            if (n >= N_NODES) n = N_NODES - 1;
            float4 v = __ldg(&S4[(size_t)n * (KDIM / 4) + rs * 16 + cc]);
            *(float4*)&As[rr][cc * 4] = v;   // stride 272B: 16B-aligned
        }
        __syncthreads();

        // tf32 mma over the 64-wide K slice
        #pragma unroll
        for (int ks = 0; ks < 8; ks++) {
            const int k0 = ks * 8;
            uint32_t a0 = f2tf32(As[wr + gid][k0 + kc]);
            uint32_t a1 = f2tf32(As[wr + gid + 8][k0 + kc]);
            uint32_t a2 = f2tf32(As[wr + gid][k0 + kc + 4]);
            uint32_t a3 = f2tf32(As[wr + gid + 8][k0 + kc + 4]);
            #pragma unroll
            for (int nt = 0; nt < 8; nt++) {
                uint32_t b0 = Ws[(k0 + kc) * W_STRIDE + nt * 8 + gid];
                uint32_t b1 = Ws[(k0 + kc + 4) * W_STRIDE + nt * 8 + gid];
                asm volatile(
                    "mma.sync.aligned.m16n8k8.row.col.f32.tf32.tf32.f32 "
                    "{%0,%1,%2,%3}, {%4,%5,%6,%7}, {%8,%9}, {%0,%1,%2,%3};"
                    : "+f"(c[nt][0]), "+f"(c[nt][1]), "+f"(c[nt][2]), "+f"(c[nt][3])
                    : "r"(a0), "r"(a1), "r"(a2), "r"(a3), "r"(b0), "r"(b1));
            }
        }
    }

    // fused epilogue: out = deg>0 ? relu(0.2*feat + (0.8/deg)*M) : feat
    {
        int r0 = row0 + wr + gid;
        int r1 = r0 + 8;
        bool v0 = r0 < N_NODES, v1 = r1 < N_NODES;
        int dg0 = v0 ? g_deg[r0] : 0;
        int dg1 = v1 ? g_deg[r1] : 0;
        float inv0 = dg0 > 0 ? 0.8f / (float)dg0 : 0.f;
        float inv1 = dg1 > 0 ? 0.8f / (float)dg1 : 0.f;
        #pragma unroll
        for (int nt = 0; nt < 8; nt++) {
            int col = nt * 8 + 2 * kc;
            if (v0) {
                float2 f = *(const float2*)&feat[(size_t)r0 * FDIM + col];
                float2 o;
                if (dg0 > 0) {
                    o.x = fmaxf(fmaf(c[nt][0], inv0, 0.2f * f.x), 0.f);
                    o.y = fmaxf(fmaf(c[nt][1], inv0, 0.2f * f.y), 0.f);
                } else o = f;
                *(float2*)&out[(size_t)r0 * FDIM + col] = o;
            }
            if (v1) {
                float2 f = *(const float2*)&feat[(size_t)r1 * FDIM + col];
                float2 o;
                if (dg1 > 0) {
                    o.x = fmaxf(fmaf(c[nt][2], inv1, 0.2f * f.x), 0.f);
                    o.y = fmaxf(fmaf(c[nt][3], inv1, 0.2f * f.y), 0.f);
                } else o = f;
                *(float2*)&out[(size_t)r1 * FDIM + col] = o;
            }
        }
    }
}

// ---------------------------------------------------------------------------
extern "C" void kernel_launch(void* const* d_in, const int* in_sizes, int n_in,
                              void* d_out, int out_size) {
    const float* feat = (const float*)d_in[0];   // [50000, 64] f32
    const float* W    = (const float*)d_in[1];   // [8, 64, 64] f32
    const int*   src  = (const int*)d_in[2];     // [800000] i32
    const int*   dst  = (const int*)d_in[3];     // [800000] i32
    const int*   et   = (const int*)d_in[4];     // [800000] i32
    float* out = (float*)d_out;                  // [50000, 64] f32

    static bool attr_set = false;
    if (!attr_set) {
        cudaFuncSetAttribute(k_gemm_final,
                             cudaFuncAttributeMaxDynamicSharedMemorySize, GEMM_SMEM);
        attr_set = true;
    }

    const size_t ZN = (size_t)N_NODES * (KDIM / 4);          // 6.4M float4
    k_zero<<<(int)((ZN + 255) / 256), 256>>>();
    k_pack_deg<<<(N_EDGES + 255) / 256, 256>>>(src, dst, et);
    k_scatter<<<(N_EDGES * 16 + 255) / 256, 256>>>((const float4*)feat);
    k_gemm_final<<<(N_NODES + 127) / 128, GT, GEMM_SMEM>>>(feat, W, out);
}